// round 13
// baseline (speedup 1.0000x reference)
#include <cuda_runtime.h>
#include <cuda_fp16.h>
#include <string.h>

#define D128 128
#define H0 64
#define W0 96
#define HW0 (H0 * W0)   // 6144

// f1: fp32 pyramid. f2: fp16 pyramid. Offsets: L0 0, L1 786432, L2 983040, L3 1032192.
__device__ __align__(16) float  g_f1[1044480];
__device__ __align__(16) __half g_f2h[1044480];

typedef unsigned long long ull;

__device__ __forceinline__ void fma2(ull& d, ull a, ull b) {
    asm("fma.rn.f32x2 %0, %1, %2, %3;" : "=l"(d) : "l"(a), "l"(b), "l"(d));
}
__device__ __forceinline__ ull pk2(float2 v) {
    ull r; memcpy(&r, &v, 8); return r;
}

// ---------------------------------------------------------------------------
// Kernel 1: fused transpose + pyramid build, 32-channel slices.
// grid (96, 4, 2): x = 8x8 pixel tile, y = channel slice, z = map.
// map 0 -> fp32 g_f1; map 1 -> fp16 g_f2h.
// ---------------------------------------------------------------------------
__global__ __launch_bounds__(512) void build_kernel(const float* __restrict__ f1,
                                                    const float* __restrict__ f2) {
    __shared__ float s0[8][8][32];   // 8KB
    __shared__ float s1[4][4][32];   // 2KB
    __shared__ float s2[2][2][32];   // 0.5KB
    int map = blockIdx.z;
    int cB  = blockIdx.y * 32;
    const float* in = map ? f2 : f1;
    int tx0 = (blockIdx.x % 12) * 8;
    int ty0 = (blockIdx.x / 12) * 8;
    int t = threadIdx.x;

    // load: local ch d = t>>4, row r8 = (t>>1)&7, half = t&1 -> one float4
    {
        int d    = t >> 4;
        int r8   = (t >> 1) & 7;
        int half = t & 1;
        const float* src = in + (cB + d) * HW0 + (ty0 + r8) * W0 + tx0 + half * 4;
        float4 v = *(const float4*)src;
        int xb = half * 4;
        s0[r8][xb + 0][d] = v.x;  s0[r8][xb + 1][d] = v.y;
        s0[r8][xb + 2][d] = v.z;  s0[r8][xb + 3][d] = v.w;
    }
    __syncthreads();

    // transposed L0: 64 px x 8 float4-chunks of 32ch = 512, 1/thread
    {
        int c4 = t & 7;
        int px = t >> 3;            // 0..63
        int y = px >> 3, x = px & 7;
        float4 w = *(float4*)&s0[y][x][c4 * 4];
        int go = ((ty0 + y) * W0 + tx0 + x) * D128 + cB + c4 * 4;
        if (map == 0) {
            *(float4*)(g_f1 + go) = w;
        } else {
            __half2 h0 = __floats2half2_rn(w.x, w.y);
            __half2 h1 = __floats2half2_rn(w.z, w.w);
            uint2 pk = make_uint2(*(unsigned*)&h0, *(unsigned*)&h1);
            *(uint2*)(g_f2h + go) = pk;
        }
    }

    // L1: 16 px x 32 ch = 512, 1/thread
    {
        int c = t & 31;
        int px = t >> 5;            // 0..15
        int y = px >> 2, x = px & 3;
        float r = 0.25f * (s0[2*y][2*x][c] + s0[2*y][2*x+1][c]
                         + s0[2*y+1][2*x][c] + s0[2*y+1][2*x+1][c]);
        s1[y][x][c] = r;
        int go = 786432 + ((ty0 / 2 + y) * 48 + tx0 / 2 + x) * D128 + cB + c;
        if (map == 0) g_f1[go] = r;
        else          g_f2h[go] = __float2half(r);
    }
    __syncthreads();

    // L2: 4 px x 32 ch = 128
    if (t < 128) {
        int c = t & 31;
        int px = t >> 5;
        int y = px >> 1, x = px & 1;
        float r = 0.25f * (s1[2*y][2*x][c] + s1[2*y][2*x+1][c]
                         + s1[2*y+1][2*x][c] + s1[2*y+1][2*x+1][c]);
        s2[y][x][c] = r;
        int go = 983040 + ((ty0 / 4 + y) * 24 + tx0 / 4 + x) * D128 + cB + c;
        if (map == 0) g_f1[go] = r;
        else          g_f2h[go] = __float2half(r);
    }
    __syncthreads();

    // L3: 1 px x 32 ch
    if (t < 32) {
        float r = 0.25f * (s2[0][0][t] + s2[0][1][t] + s2[1][0][t] + s2[1][1][t]);
        int go = 1032192 + ((ty0 / 8) * 12 + tx0 / 8) * D128 + cB + t;
        if (map == 0) g_f1[go] = r;
        else          g_f2h[go] = __float2half(r);
    }
}

// ---------------------------------------------------------------------------
// Kernel 2: fused correlation. 512 threads = 16 warps; ONE WARP PER PIXEL.
// All pre-combine work is warp-local -> single __syncthreads in the kernel.
// Dot: 25 passes x 4 positions (exactly 100), fp16 f2 loads, cvt + packed
// fma.rn.f32x2, fp32 accumulate, 3x shfl reduce per position.
// ---------------------------------------------------------------------------
__global__ __launch_bounds__(512, 3) void corr_kernel(const float* __restrict__ coords,
                                                      float* __restrict__ out) {
    int g16 = (blockIdx.x % 148) * 4 + blockIdx.x / 148;
    if (g16 >= 510) return;

    int lvl, q;
    if (g16 < 384)      { lvl = 0; q = g16; }
    else if (g16 < 480) { lvl = 1; q = g16 - 384; }
    else if (g16 < 504) { lvl = 2; q = g16 - 480; }
    else                { lvl = 3; q = g16 - 504; }

    int loff, ooff;
    switch (lvl) {
        case 0:  loff = 0;       ooff = 0;      break;
        case 1:  loff = 786432;  ooff = 497664; break;
        case 2:  loff = 983040;  ooff = 622080; break;
        default: loff = 1032192; ooff = 653184; break;
    }
    const int Hl = H0 >> lvl, Wl = W0 >> lvl;

    int t    = threadIdx.x;
    int w    = t >> 5;          // warp = pixel 0..15
    int lane = t & 31;
    int sub  = lane & 7;
    int quad = lane >> 3;
    int p    = 16 * q + w;
    int py = p / Wl, px = p - py * Wl;

    __shared__ float sh_c[16][2];
    __shared__ int   sh_addr[16][100];
    __shared__ float sh_dot[16][101];   // stride 101: conflict-free combine

    // --- f1 fp32 chunks (broadcast across quads); issue LDGs first
    const float4* f1v = (const float4*)(g_f1 + loff + p * D128);
    float4 a0 = f1v[2 * sub];
    float4 a1 = f1v[2 * sub + 1];
    float4 a2 = f1v[16 + 2 * sub];
    float4 a3 = f1v[17 + 2 * sub];

    // --- coords for this warp's pixel (jax.image.resize linear antialias)
    float cx, cy;
    if (lvl == 0) {
        float c = 0.f;
        if (lane < 2) c = coords[lane * HW0 + p];
        cx = __shfl_sync(0xffffffffu, c, 0);
        cy = __shfl_sync(0xffffffffu, c, 1);
        if (lane < 2) sh_c[w][lane] = c;
    } else {
        int   f    = 1 << lvl;
        float invf = 1.0f / (float)f;
        float sy = ((float)py + 0.5f) * (float)f - 0.5f;
        float sx = ((float)px + 0.5f) * (float)f - 0.5f;
        int jylo = max(0,      (int)floorf(sy - (float)f) + 1);
        int jyhi = min(H0 - 1, (int)floorf(sy + (float)f));
        int jxlo = max(0,      (int)floorf(sx - (float)f) + 1);
        int jxhi = min(W0 - 1, (int)floorf(sx + (float)f));
        int jx = jxlo + (lane & 15);
        bool okx = (jx <= jxhi);
        float wx = okx ? (1.f - fabsf(sx - (float)jx) * invf) : 0.f;
        float acc0 = 0.f, acc1 = 0.f, ws = 0.f;
        for (int jy = jylo + (lane >> 4); jy <= jyhi; jy += 2) {
            float wy = 1.f - fabsf(sy - (float)jy) * invf;
            float ww = wy * wx;
            if (okx) {
                acc0 += ww * coords[jy * W0 + jx];
                acc1 += ww * coords[HW0 + jy * W0 + jx];
                ws   += ww;
            }
        }
#pragma unroll
        for (int m = 16; m; m >>= 1) {
            acc0 += __shfl_xor_sync(0xffffffffu, acc0, m);
            acc1 += __shfl_xor_sync(0xffffffffu, acc1, m);
            ws   += __shfl_xor_sync(0xffffffffu, ws,   m);
        }
        float inv = invf / ws;
        cx = acc0 * inv;
        cy = acc1 * inv;
        if (lane == 0) { sh_c[w][0] = cx; sh_c[w][1] = cy; }
    }

    int ix = (int)floorf(cx);
    int iy = (int)floorf(cy);

    // --- tap base addresses (uint4 units), warp-local
#pragma unroll
    for (int idx = lane; idx < 100; idx += 32) {
        int ty = idx / 10, tx = idx - ty * 10;
        int gy = min(max(iy + ty - 4, 0), Hl - 1);
        int gx = min(max(ix + tx - 4, 0), Wl - 1);
        sh_addr[w][idx] = (gy * Wl + gx) * 16;
    }
    __syncwarp();

    // pack f1 pairs for fma2 (pairs match half2 lanes of the fp16 loads)
    ull A0, A1, A2, A3, A4, A5, A6, A7;
    { ulonglong2 u; memcpy(&u, &a0, 16); A0 = u.x; A1 = u.y; }
    { ulonglong2 u; memcpy(&u, &a1, 16); A2 = u.x; A3 = u.y; }
    { ulonglong2 u; memcpy(&u, &a2, 16); A4 = u.x; A5 = u.y; }
    { ulonglong2 u; memcpy(&u, &a3, 16); A6 = u.x; A7 = u.y; }

    const uint4* f2base = (const uint4*)(g_f2h + loff);

    // --- 100 dots: 25 passes x 4 positions (quad owns one per pass)
#pragma unroll 5
    for (int j = 0; j < 25; j++) {
        int pos = j * 4 + quad;           // exactly 0..99
        const uint4* qv = f2base + sh_addr[w][pos];
        uint4 r0 = qv[sub];
        uint4 r1 = qv[8 + sub];
        const __half2* h0 = (const __half2*)&r0;
        const __half2* h1 = (const __half2*)&r1;
        ull acc = 0ULL;
        fma2(acc, A0, pk2(__half22float2(h0[0])));
        fma2(acc, A1, pk2(__half22float2(h0[1])));
        fma2(acc, A2, pk2(__half22float2(h0[2])));
        fma2(acc, A3, pk2(__half22float2(h0[3])));
        fma2(acc, A4, pk2(__half22float2(h1[0])));
        fma2(acc, A5, pk2(__half22float2(h1[1])));
        fma2(acc, A6, pk2(__half22float2(h1[2])));
        fma2(acc, A7, pk2(__half22float2(h1[3])));
        float2 fr; memcpy(&fr, &acc, 8);
        float s = fr.x + fr.y;
        s += __shfl_xor_sync(0xffffffffu, s, 1);
        s += __shfl_xor_sync(0xffffffffu, s, 2);
        s += __shfl_xor_sync(0xffffffffu, s, 4);
        if (sub == 0) sh_dot[w][pos] = s;
    }
    __syncthreads();   // the ONLY block barrier

    // --- bilinear combine: 1296 outputs (81 k x 16 px), 64B-contig stores
    for (int idx = t; idx < 1296; idx += 512) {
        int k  = idx >> 4;
        int sd = idx & 15;
        float cx2 = sh_c[sd][0], cy2 = sh_c[sd][1];
        int ix2 = (int)floorf(cx2);
        int iy2 = (int)floorf(cy2);
        int dxi = k / 9, dyi = k - dxi * 9;
        float xq = fminf(fmaxf(cx2 + (float)(dxi - 4), 0.f), (float)(Wl - 1));
        float yq = fminf(fmaxf(cy2 + (float)(dyi - 4), 0.f), (float)(Hl - 1));
        float x0f = floorf(xq), y0f = floorf(yq);
        float wx1 = xq - x0f,  wy1 = yq - y0f;
        float wx0 = 1.f - wx1, wy0 = 1.f - wy1;
        int t0x = min(max((int)x0f - ix2 + 4, 0), 9), t1x = min(t0x + 1, 9);
        int t0y = min(max((int)y0f - iy2 + 4, 0), 9), t1y = min(t0y + 1, 9);
        float v = wy0 * (wx0 * sh_dot[sd][t0y * 10 + t0x] + wx1 * sh_dot[sd][t0y * 10 + t1x])
                + wy1 * (wx0 * sh_dot[sd][t1y * 10 + t0x] + wx1 * sh_dot[sd][t1y * 10 + t1x]);
        out[ooff + k * (Hl * Wl) + 16 * q + sd] = v * 0.08838834764831845f;  // 1/sqrt(128)
    }
}

// ---------------------------------------------------------------------------
extern "C" void kernel_launch(void* const* d_in, const int* in_sizes, int n_in,
                              void* d_out, int out_size) {
    const float* f1     = (const float*)d_in[0];
    const float* f2     = (const float*)d_in[1];
    const float* coords = (const float*)d_in[2];
    float* out = (float*)d_out;

    build_kernel<<<dim3(96, 4, 2), 512>>>(f1, f2);
    // 148 * 4 = 592 blocks cover 510 pixel-16-groups, SM-contiguous mapping
    corr_kernel<<<592, 512>>>(coords, out);
}

// round 14
// speedup vs baseline: 1.0688x; 1.0688x over previous
#include <cuda_runtime.h>
#include <cuda_fp16.h>
#include <string.h>

#define D128 128
#define H0 64
#define W0 96
#define HW0 (H0 * W0)   // 6144

// f1: fp32 pyramid. f2: fp16 pyramid. Offsets: L0 0, L1 786432, L2 983040, L3 1032192.
__device__ __align__(16) float  g_f1[1044480];
__device__ __align__(16) __half g_f2h[1044480];

typedef unsigned long long ull;

__device__ __forceinline__ void fma2(ull& d, ull a, ull b) {
    asm("fma.rn.f32x2 %0, %1, %2, %3;" : "=l"(d) : "l"(a), "l"(b), "l"(d));
}
__device__ __forceinline__ ull pk2(float2 v) {
    ull r; memcpy(&r, &v, 8); return r;
}

// ---------------------------------------------------------------------------
// Kernel 1: fused transpose + pyramid build (R12 version, 64-ch slices).
// grid (96, 2, 2): x = 8x8 tile, y = channel slice, z = map.
// ---------------------------------------------------------------------------
__global__ __launch_bounds__(512) void build_kernel(const float* __restrict__ f1,
                                                    const float* __restrict__ f2) {
    __shared__ float s0[8][8][64];   // 16KB
    __shared__ float s1[4][4][64];   // 4KB
    __shared__ float s2[2][2][64];   // 1KB
    int map = blockIdx.z;
    int cB  = blockIdx.y * 64;
    const float* in = map ? f2 : f1;
    int tx0 = (blockIdx.x % 12) * 8;
    int ty0 = (blockIdx.x / 12) * 8;
    int t = threadIdx.x;

    {
        int d  = t >> 3;
        int sl = t & 7;
        const float* src = in + (cB + d) * HW0 + (ty0 + sl) * W0 + tx0;
        float4 v0 = *(const float4*)(src);
        float4 v1 = *(const float4*)(src + 4);
        s0[sl][0][d] = v0.x; s0[sl][1][d] = v0.y; s0[sl][2][d] = v0.z; s0[sl][3][d] = v0.w;
        s0[sl][4][d] = v1.x; s0[sl][5][d] = v1.y; s0[sl][6][d] = v1.z; s0[sl][7][d] = v1.w;
    }
    __syncthreads();

#pragma unroll
    for (int i = 0; i < 2; i++) {
        int idx = i * 512 + t;
        int c4 = idx & 15;
        int px = idx >> 4;
        int y = px >> 3, x = px & 7;
        float4 w = *(float4*)&s0[y][x][c4 * 4];
        int go = ((ty0 + y) * W0 + tx0 + x) * D128 + cB + c4 * 4;
        if (map == 0) {
            *(float4*)(g_f1 + go) = w;
        } else {
            __half2 h0 = __floats2half2_rn(w.x, w.y);
            __half2 h1 = __floats2half2_rn(w.z, w.w);
            uint2 pk = make_uint2(*(unsigned*)&h0, *(unsigned*)&h1);
            *(uint2*)(g_f2h + go) = pk;
        }
    }

#pragma unroll
    for (int i = 0; i < 2; i++) {
        int idx = i * 512 + t;
        int c = idx & 63;
        int px = idx >> 6;
        int y = px >> 2, x = px & 3;
        float r = 0.25f * (s0[2*y][2*x][c] + s0[2*y][2*x+1][c]
                         + s0[2*y+1][2*x][c] + s0[2*y+1][2*x+1][c]);
        s1[y][x][c] = r;
        int go = 786432 + ((ty0 / 2 + y) * 48 + tx0 / 2 + x) * D128 + cB + c;
        if (map == 0) g_f1[go] = r;
        else          g_f2h[go] = __float2half(r);
    }
    __syncthreads();

    if (t < 256) {
        int c = t & 63;
        int px = t >> 6;
        int y = px >> 1, x = px & 1;
        float r = 0.25f * (s1[2*y][2*x][c] + s1[2*y][2*x+1][c]
                         + s1[2*y+1][2*x][c] + s1[2*y+1][2*x+1][c]);
        s2[y][x][c] = r;
        int go = 983040 + ((ty0 / 4 + y) * 24 + tx0 / 4 + x) * D128 + cB + c;
        if (map == 0) g_f1[go] = r;
        else          g_f2h[go] = __float2half(r);
    }
    __syncthreads();

    if (t < 64) {
        float r = 0.25f * (s2[0][0][t] + s2[0][1][t] + s2[1][0][t] + s2[1][1][t]);
        int go = 1032192 + ((ty0 / 8) * 12 + tx0 / 8) * D128 + cB + t;
        if (map == 0) g_f1[go] = r;
        else          g_f2h[go] = __float2half(r);
    }
}

// ---------------------------------------------------------------------------
// Kernel 2: fused correlation (R12 base). 512 threads, 8 pixels per block
// (side = t>>6, 2 warps/pixel in the dot phase). CHANGE vs R12: the coords
// warp (one per pixel) also computes that pixel's tap addresses warp-locally,
// eliminating the coords->addr block barrier (2 barriers pre-combine -> 1).
// ---------------------------------------------------------------------------
__global__ __launch_bounds__(512) void corr_kernel(const float* __restrict__ coords,
                                                   float* __restrict__ out) {
    int g8 = (blockIdx.x % 148) * 7 + blockIdx.x / 148;
    if (g8 >= 1020) return;

    int lvl, q;
    if (g8 < 768)       { lvl = 0; q = g8; }
    else if (g8 < 960)  { lvl = 1; q = g8 - 768; }
    else if (g8 < 1008) { lvl = 2; q = g8 - 960; }
    else                { lvl = 3; q = g8 - 1008; }

    int loff, ooff;
    switch (lvl) {
        case 0:  loff = 0;       ooff = 0;      break;
        case 1:  loff = 786432;  ooff = 497664; break;
        case 2:  loff = 983040;  ooff = 622080; break;
        default: loff = 1032192; ooff = 653184; break;
    }
    const int Hl = H0 >> lvl, Wl = W0 >> lvl;

    int t    = threadIdx.x;
    int side = t >> 6;          // pixel 0..7 of the octet
    int tt   = t & 63;
    int p    = 8 * q + side;

    __shared__ float sh_c[8][2];
    __shared__ int   sh_addr[8][104];
    __shared__ float sh_dot[8][104];

    int w2   = tt >> 5;         // warp-within-side 0..1
    int lane = t & 31;
    int sub  = lane & 7;
    int quad = lane >> 3;

    // --- f1 fp32 chunks for this lane; issue LDGs before coords work
    const float4* f1v = (const float4*)(g_f1 + loff + p * D128);
    float4 a0 = f1v[2 * sub];
    float4 a1 = f1v[2 * sub + 1];
    float4 a2 = f1v[16 + 2 * sub];
    float4 a3 = f1v[17 + 2 * sub];

    // --- coords + tap addresses: warps 0..7, one pixel each, warp-local.
    if (t < 256) {
        int wpix = t >> 5;      // 0..7
        int pc = 8 * q + wpix;
        int pyc = pc / Wl, pxc = pc - pyc * Wl;
        float cxw, cyw;
        if (lvl == 0) {
            float c = 0.f;
            if (lane < 2) c = coords[lane * HW0 + pc];
            cxw = __shfl_sync(0xffffffffu, c, 0);
            cyw = __shfl_sync(0xffffffffu, c, 1);
        } else {
            // jax.image.resize linear antialias: triangle kernel scale
            // f=2^lvl, normalized by in-range weight sum, then /f.
            int   f    = 1 << lvl;
            float invf = 1.0f / (float)f;
            float sy = ((float)pyc + 0.5f) * (float)f - 0.5f;
            float sx = ((float)pxc + 0.5f) * (float)f - 0.5f;
            int jylo = max(0,      (int)floorf(sy - (float)f) + 1);
            int jyhi = min(H0 - 1, (int)floorf(sy + (float)f));
            int jxlo = max(0,      (int)floorf(sx - (float)f) + 1);
            int jxhi = min(W0 - 1, (int)floorf(sx + (float)f));
            int jx = jxlo + (lane & 15);
            bool okx = (jx <= jxhi);
            float wx = okx ? (1.f - fabsf(sx - (float)jx) * invf) : 0.f;
            float acc0 = 0.f, acc1 = 0.f, ws = 0.f;
            for (int jy = jylo + (lane >> 4); jy <= jyhi; jy += 2) {
                float wy = 1.f - fabsf(sy - (float)jy) * invf;
                float ww = wy * wx;
                if (okx) {
                    acc0 += ww * coords[jy * W0 + jx];
                    acc1 += ww * coords[HW0 + jy * W0 + jx];
                    ws   += ww;
                }
            }
#pragma unroll
            for (int m = 16; m; m >>= 1) {
                acc0 += __shfl_xor_sync(0xffffffffu, acc0, m);
                acc1 += __shfl_xor_sync(0xffffffffu, acc1, m);
                ws   += __shfl_xor_sync(0xffffffffu, ws,   m);
            }
            float inv = invf / ws;
            cxw = acc0 * inv;
            cyw = acc1 * inv;
        }
        if (lane == 0) { sh_c[wpix][0] = cxw; sh_c[wpix][1] = cyw; }

        // tap addresses for this pixel, same warp (uint4 units; pad 100..103)
        int ixw = (int)floorf(cxw);
        int iyw = (int)floorf(cyw);
#pragma unroll
        for (int idx = lane; idx < 104; idx += 32) {
            int ty = idx / 10, tx = idx - ty * 10;
            int gy = min(max(iyw + ty - 4, 0), Hl - 1);
            int gx = min(max(ixw + tx - 4, 0), Wl - 1);
            sh_addr[wpix][idx] = (idx < 100) ? (gy * Wl + gx) * 16 : 0;
        }
    }
    __syncthreads();

    // pack f1 pairs for fma2 (pairs match half2 lanes of the fp16 loads)
    ull A0, A1, A2, A3, A4, A5, A6, A7;
    { ulonglong2 u; memcpy(&u, &a0, 16); A0 = u.x; A1 = u.y; }
    { ulonglong2 u; memcpy(&u, &a1, 16); A2 = u.x; A3 = u.y; }
    { ulonglong2 u; memcpy(&u, &a2, 16); A4 = u.x; A5 = u.y; }
    { ulonglong2 u; memcpy(&u, &a3, 16); A6 = u.x; A7 = u.y; }

    const uint4* f2base = (const uint4*)(g_f2h + loff);

    // --- 100 corner dots per side: 13 passes x (2 warps x 4 positions)
#pragma unroll
    for (int j = 0; j < 13; j++) {
        int pos = j * 8 + w2 * 4 + quad;     // 0..103 (padded addrs)
        const uint4* qv = f2base + sh_addr[side][pos];
        uint4 r0 = qv[sub];
        uint4 r1 = qv[8 + sub];
        const __half2* h0 = (const __half2*)&r0;
        const __half2* h1 = (const __half2*)&r1;
        ull acc = 0ULL;
        fma2(acc, A0, pk2(__half22float2(h0[0])));
        fma2(acc, A1, pk2(__half22float2(h0[1])));
        fma2(acc, A2, pk2(__half22float2(h0[2])));
        fma2(acc, A3, pk2(__half22float2(h0[3])));
        fma2(acc, A4, pk2(__half22float2(h1[0])));
        fma2(acc, A5, pk2(__half22float2(h1[1])));
        fma2(acc, A6, pk2(__half22float2(h1[2])));
        fma2(acc, A7, pk2(__half22float2(h1[3])));
        float2 fr; memcpy(&fr, &acc, 8);
        float s = fr.x + fr.y;
        s += __shfl_xor_sync(0xffffffffu, s, 1);
        s += __shfl_xor_sync(0xffffffffu, s, 2);
        s += __shfl_xor_sync(0xffffffffu, s, 4);
        if (sub == 0 && pos < 100) sh_dot[side][pos] = s;
    }
    __syncthreads();

    // --- bilinear combine: 648 outputs (81 k x 8 px), 32B-contiguous stores
    for (int idx = t; idx < 648; idx += 512) {
        int k  = idx >> 3;
        int sd = idx & 7;
        float cx2 = sh_c[sd][0], cy2 = sh_c[sd][1];
        int ix2 = (int)floorf(cx2);
        int iy2 = (int)floorf(cy2);
        int dxi = k / 9, dyi = k - dxi * 9;
        float xq = fminf(fmaxf(cx2 + (float)(dxi - 4), 0.f), (float)(Wl - 1));
        float yq = fminf(fmaxf(cy2 + (float)(dyi - 4), 0.f), (float)(Hl - 1));
        float x0f = floorf(xq), y0f = floorf(yq);
        float wx1 = xq - x0f,  wy1 = yq - y0f;
        float wx0 = 1.f - wx1, wy0 = 1.f - wy1;
        int t0x = min(max((int)x0f - ix2 + 4, 0), 9), t1x = min(t0x + 1, 9);
        int t0y = min(max((int)y0f - iy2 + 4, 0), 9), t1y = min(t0y + 1, 9);
        float v = wy0 * (wx0 * sh_dot[sd][t0y * 10 + t0x] + wx1 * sh_dot[sd][t0y * 10 + t1x])
                + wy1 * (wx0 * sh_dot[sd][t1y * 10 + t0x] + wx1 * sh_dot[sd][t1y * 10 + t1x]);
        out[ooff + k * (Hl * Wl) + 8 * q + sd] = v * 0.08838834764831845f;  // 1/sqrt(128)
    }
}

// ---------------------------------------------------------------------------
extern "C" void kernel_launch(void* const* d_in, const int* in_sizes, int n_in,
                              void* d_out, int out_size) {
    const float* f1     = (const float*)d_in[0];
    const float* f2     = (const float*)d_in[1];
    const float* coords = (const float*)d_in[2];
    float* out = (float*)d_out;

    build_kernel<<<dim3(96, 2, 2), 512>>>(f1, f2);
    // 148 * 7 = 1036 blocks cover 1020 pixel-octets, SM-contiguous mapping
    corr_kernel<<<1036, 512>>>(coords, out);
}

// round 15
// speedup vs baseline: 1.1389x; 1.0656x over previous
#include <cuda_runtime.h>
#include <cuda_fp16.h>
#include <string.h>

#define D128 128
#define H0 64
#define W0 96
#define HW0 (H0 * W0)   // 6144

// BOTH pyramids fp16. Offsets (elements): L0 0, L1 786432, L2 983040, L3 1032192.
__device__ __align__(16) __half g_f1h[1044480];
__device__ __align__(16) __half g_f2h[1044480];

// ---------------------------------------------------------------------------
// Kernel 1: fused transpose + pyramid build, 64-ch slices, fp16 out.
// grid (96, 2, 2): x = 8x8 tile, y = channel slice, z = map.
// Pool math in fp32 (SMEM), single quantization per level.
// ---------------------------------------------------------------------------
__global__ __launch_bounds__(512) void build_kernel(const float* __restrict__ f1,
                                                    const float* __restrict__ f2) {
    __shared__ float s0[8][8][64];   // 16KB
    __shared__ float s1[4][4][64];   // 4KB
    __shared__ float s2[2][2][64];   // 1KB
    int map = blockIdx.z;
    int cB  = blockIdx.y * 64;
    const float* in = map ? f2 : f1;
    __half* base = map ? g_f2h : g_f1h;
    int tx0 = (blockIdx.x % 12) * 8;
    int ty0 = (blockIdx.x / 12) * 8;
    int t = threadIdx.x;

    {
        int d  = t >> 3;
        int sl = t & 7;
        const float* src = in + (cB + d) * HW0 + (ty0 + sl) * W0 + tx0;
        float4 v0 = *(const float4*)(src);
        float4 v1 = *(const float4*)(src + 4);
        s0[sl][0][d] = v0.x; s0[sl][1][d] = v0.y; s0[sl][2][d] = v0.z; s0[sl][3][d] = v0.w;
        s0[sl][4][d] = v1.x; s0[sl][5][d] = v1.y; s0[sl][6][d] = v1.z; s0[sl][7][d] = v1.w;
    }
    __syncthreads();

    // transposed L0, fp16: 64 px x 16 chunks of 4ch = 1024, 2/thread
#pragma unroll
    for (int i = 0; i < 2; i++) {
        int idx = i * 512 + t;
        int c4 = idx & 15;
        int px = idx >> 4;
        int y = px >> 3, x = px & 7;
        float4 w = *(float4*)&s0[y][x][c4 * 4];
        int go = ((ty0 + y) * W0 + tx0 + x) * D128 + cB + c4 * 4;
        __half2 h0 = __floats2half2_rn(w.x, w.y);
        __half2 h1 = __floats2half2_rn(w.z, w.w);
        uint2 pk = make_uint2(*(unsigned*)&h0, *(unsigned*)&h1);
        *(uint2*)(base + go) = pk;
    }

    // L1: 16 px x 64 ch = 1024, 2/thread
#pragma unroll
    for (int i = 0; i < 2; i++) {
        int idx = i * 512 + t;
        int c = idx & 63;
        int px = idx >> 6;
        int y = px >> 2, x = px & 3;
        float r = 0.25f * (s0[2*y][2*x][c] + s0[2*y][2*x+1][c]
                         + s0[2*y+1][2*x][c] + s0[2*y+1][2*x+1][c]);
        s1[y][x][c] = r;
        int go = 786432 + ((ty0 / 2 + y) * 48 + tx0 / 2 + x) * D128 + cB + c;
        base[go] = __float2half(r);
    }
    __syncthreads();

    // L2: 4 px x 64 ch = 256
    if (t < 256) {
        int c = t & 63;
        int px = t >> 6;
        int y = px >> 1, x = px & 1;
        float r = 0.25f * (s1[2*y][2*x][c] + s1[2*y][2*x+1][c]
                         + s1[2*y+1][2*x][c] + s1[2*y+1][2*x+1][c]);
        s2[y][x][c] = r;
        int go = 983040 + ((ty0 / 4 + y) * 24 + tx0 / 4 + x) * D128 + cB + c;
        base[go] = __float2half(r);
    }
    __syncthreads();

    // L3: 1 px x 64 ch
    if (t < 64) {
        float r = 0.25f * (s2[0][0][t] + s2[0][1][t] + s2[1][0][t] + s2[1][1][t]);
        int go = 1032192 + ((ty0 / 8) * 12 + tx0 / 8) * D128 + cB + t;
        base[go] = __float2half(r);
    }
}

// ---------------------------------------------------------------------------
// Kernel 2: fused correlation (R14 structure). 512 threads, 8 px/block.
// Coords warp also builds tap addresses (1 pre-combine barrier).
// Dot: fp16 x fp16 via 8 HFMA2 (length-8 fp16 chains), one cvt per pass,
// fp32 across passes.
// ---------------------------------------------------------------------------
__global__ __launch_bounds__(512) void corr_kernel(const float* __restrict__ coords,
                                                   float* __restrict__ out) {
    int g8 = (blockIdx.x % 148) * 7 + blockIdx.x / 148;
    if (g8 >= 1020) return;

    int lvl, q;
    if (g8 < 768)       { lvl = 0; q = g8; }
    else if (g8 < 960)  { lvl = 1; q = g8 - 768; }
    else if (g8 < 1008) { lvl = 2; q = g8 - 960; }
    else                { lvl = 3; q = g8 - 1008; }

    int loff, ooff;
    switch (lvl) {
        case 0:  loff = 0;       ooff = 0;      break;
        case 1:  loff = 786432;  ooff = 497664; break;
        case 2:  loff = 983040;  ooff = 622080; break;
        default: loff = 1032192; ooff = 653184; break;
    }
    const int Hl = H0 >> lvl, Wl = W0 >> lvl;

    int t    = threadIdx.x;
    int side = t >> 6;          // pixel 0..7 of the octet
    int tt   = t & 63;
    int p    = 8 * q + side;

    __shared__ float sh_c[8][2];
    __shared__ int   sh_addr[8][104];
    __shared__ float sh_dot[8][104];

    int w2   = tt >> 5;         // warp-within-side 0..1
    int lane = t & 31;
    int sub  = lane & 7;
    int quad = lane >> 3;

    // --- f1 fp16 chunks for this lane (chs 8sub..8sub+7 and 64+8sub..)
    const uint4* f1v = (const uint4*)(g_f1h + loff + p * D128);
    uint4 A0 = f1v[sub];
    uint4 A1 = f1v[8 + sub];

    // --- coords + tap addresses: warps 0..7, one pixel each, warp-local.
    if (t < 256) {
        int wpix = t >> 5;      // 0..7
        int pc = 8 * q + wpix;
        int pyc = pc / Wl, pxc = pc - pyc * Wl;
        float cxw, cyw;
        if (lvl == 0) {
            float c = 0.f;
            if (lane < 2) c = coords[lane * HW0 + pc];
            cxw = __shfl_sync(0xffffffffu, c, 0);
            cyw = __shfl_sync(0xffffffffu, c, 1);
        } else {
            // jax.image.resize linear antialias: triangle kernel scale
            // f=2^lvl, normalized by in-range weight sum, then /f.
            int   f    = 1 << lvl;
            float invf = 1.0f / (float)f;
            float sy = ((float)pyc + 0.5f) * (float)f - 0.5f;
            float sx = ((float)pxc + 0.5f) * (float)f - 0.5f;
            int jylo = max(0,      (int)floorf(sy - (float)f) + 1);
            int jyhi = min(H0 - 1, (int)floorf(sy + (float)f));
            int jxlo = max(0,      (int)floorf(sx - (float)f) + 1);
            int jxhi = min(W0 - 1, (int)floorf(sx + (float)f));
            int jx = jxlo + (lane & 15);
            bool okx = (jx <= jxhi);
            float wx = okx ? (1.f - fabsf(sx - (float)jx) * invf) : 0.f;
            float acc0 = 0.f, acc1 = 0.f, ws = 0.f;
            for (int jy = jylo + (lane >> 4); jy <= jyhi; jy += 2) {
                float wy = 1.f - fabsf(sy - (float)jy) * invf;
                float ww = wy * wx;
                if (okx) {
                    acc0 += ww * coords[jy * W0 + jx];
                    acc1 += ww * coords[HW0 + jy * W0 + jx];
                    ws   += ww;
                }
            }
#pragma unroll
            for (int m = 16; m; m >>= 1) {
                acc0 += __shfl_xor_sync(0xffffffffu, acc0, m);
                acc1 += __shfl_xor_sync(0xffffffffu, acc1, m);
                ws   += __shfl_xor_sync(0xffffffffu, ws,   m);
            }
            float inv = invf / ws;
            cxw = acc0 * inv;
            cyw = acc1 * inv;
        }
        if (lane == 0) { sh_c[wpix][0] = cxw; sh_c[wpix][1] = cyw; }

        // tap addresses for this pixel, same warp (uint4 units; pad 100..103)
        int ixw = (int)floorf(cxw);
        int iyw = (int)floorf(cyw);
#pragma unroll
        for (int idx = lane; idx < 104; idx += 32) {
            int ty = idx / 10, tx = idx - ty * 10;
            int gy = min(max(iyw + ty - 4, 0), Hl - 1);
            int gx = min(max(ixw + tx - 4, 0), Wl - 1);
            sh_addr[wpix][idx] = (idx < 100) ? (gy * Wl + gx) * 16 : 0;
        }
    }
    __syncthreads();

    const __half2* ah0 = (const __half2*)&A0;
    const __half2* ah1 = (const __half2*)&A1;
    const uint4* f2base = (const uint4*)(g_f2h + loff);

    // --- 100 corner dots per side: 13 passes x (2 warps x 4 positions)
#pragma unroll
    for (int j = 0; j < 13; j++) {
        int pos = j * 8 + w2 * 4 + quad;     // 0..103 (padded addrs)
        const uint4* qv = f2base + sh_addr[side][pos];
        uint4 r0 = qv[sub];
        uint4 r1 = qv[8 + sub];
        const __half2* qh0 = (const __half2*)&r0;
        const __half2* qh1 = (const __half2*)&r1;
        __half2 acc = __floats2half2_rn(0.f, 0.f);
        acc = __hfma2(ah0[0], qh0[0], acc);
        acc = __hfma2(ah0[1], qh0[1], acc);
        acc = __hfma2(ah0[2], qh0[2], acc);
        acc = __hfma2(ah0[3], qh0[3], acc);
        acc = __hfma2(ah1[0], qh1[0], acc);
        acc = __hfma2(ah1[1], qh1[1], acc);
        acc = __hfma2(ah1[2], qh1[2], acc);
        acc = __hfma2(ah1[3], qh1[3], acc);
        float2 fr = __half22float2(acc);
        float s = fr.x + fr.y;
        s += __shfl_xor_sync(0xffffffffu, s, 1);
        s += __shfl_xor_sync(0xffffffffu, s, 2);
        s += __shfl_xor_sync(0xffffffffu, s, 4);
        if (sub == 0 && pos < 100) sh_dot[side][pos] = s;
    }
    __syncthreads();

    // --- bilinear combine: 648 outputs (81 k x 8 px), 32B-contiguous stores
    for (int idx = t; idx < 648; idx += 512) {
        int k  = idx >> 3;
        int sd = idx & 7;
        float cx2 = sh_c[sd][0], cy2 = sh_c[sd][1];
        int ix2 = (int)floorf(cx2);
        int iy2 = (int)floorf(cy2);
        int dxi = k / 9, dyi = k - dxi * 9;
        float xq = fminf(fmaxf(cx2 + (float)(dxi - 4), 0.f), (float)(Wl - 1));
        float yq = fminf(fmaxf(cy2 + (float)(dyi - 4), 0.f), (float)(Hl - 1));
        float x0f = floorf(xq), y0f = floorf(yq);
        float wx1 = xq - x0f,  wy1 = yq - y0f;
        float wx0 = 1.f - wx1, wy0 = 1.f - wy1;
        int t0x = min(max((int)x0f - ix2 + 4, 0), 9), t1x = min(t0x + 1, 9);
        int t0y = min(max((int)y0f - iy2 + 4, 0), 9), t1y = min(t0y + 1, 9);
        float v = wy0 * (wx0 * sh_dot[sd][t0y * 10 + t0x] + wx1 * sh_dot[sd][t0y * 10 + t1x])
                + wy1 * (wx0 * sh_dot[sd][t1y * 10 + t0x] + wx1 * sh_dot[sd][t1y * 10 + t1x]);
        out[ooff + k * (Hl * Wl) + 8 * q + sd] = v * 0.08838834764831845f;  // 1/sqrt(128)
    }
}

// ---------------------------------------------------------------------------
extern "C" void kernel_launch(void* const* d_in, const int* in_sizes, int n_in,
                              void* d_out, int out_size) {
    const float* f1     = (const float*)d_in[0];
    const float* f2     = (const float*)d_in[1];
    const float* coords = (const float*)d_in[2];
    float* out = (float*)d_out;

    build_kernel<<<dim3(96, 2, 2), 512>>>(f1, f2);
    // 148 * 7 = 1036 blocks cover 1020 pixel-octets, SM-contiguous mapping
    corr_kernel<<<1036, 512>>>(coords, out);
}